// round 6
// baseline (speedup 1.0000x reference)
#include <cuda_runtime.h>
#include <cstdint>

// ---------------------------------------------------------------------------
// DilatedReparamBlock fused: merge 7 BN(dwconv) branches into one exact 13x13
// depthwise conv + bias, then a single packed-fp32 (fma.rn.f32x2) conv.
// Two-pass (d=0..3, d=4..6) input-row-outer mainloop, FULLY UNROLLED so ptxas
// can software-pipeline LDS across rows; register pressure bounded per pass.
// x: [16, 384, 56, 56] fp32 -> out same shape.
// ---------------------------------------------------------------------------

#define C_CH 384
#define NB 16
#define HW 56
#define PAD 6
#define PH 68                  // 56 + 2*6 padded tile
#define IMG_PER_BLK 4
#define THREADS 224            // 4 images * 56 threads (7 x-tiles * 8 y-tiles)
#define WSTRIDE 16             // u64 (dup-weight taps) per weight row (128B)
#define W_U64_PER_IMG (13 * WSTRIDE)                    // 208
#define SMEM_IN_BYTES (IMG_PER_BLK * PH * PH * 4)       // 73984
#define SMEM_W_BYTES  (IMG_PER_BLK * W_U64_PER_IMG * 8) // 6656
#define SMEM_BYTES    (SMEM_IN_BYTES + SMEM_W_BYTES)    // 80640

// Merged weights: per channel, 13 rows x WSTRIDE u64; entry j (j<13) is the
// tap value DUPLICATED (w,w) so it is a ready FFMA2 b-operand.
__device__ unsigned long long g_Wd[C_CH * W_U64_PER_IMG];
__device__ float g_bias[C_CH];

// ---------------------------------------------------------------------------
// Kernel 1: fold the 7 BN(dwconv) branches into one 13x13 kernel + bias.
// ---------------------------------------------------------------------------
__global__ void merge_kernel(const float* __restrict__ w_lk,
                             const float* __restrict__ w_b0,
                             const float* __restrict__ w_b1,
                             const float* __restrict__ w_b2,
                             const float* __restrict__ w_b3,
                             const float* __restrict__ w_b4,
                             const float* __restrict__ w_b5,
                             const float* __restrict__ gamma,
                             const float* __restrict__ beta,
                             const float* __restrict__ mean,
                             const float* __restrict__ var) {
    int c = blockIdx.x;
    int t = threadIdx.x;

    float inv[7];
#pragma unroll
    for (int m = 0; m < 7; m++)
        inv[m] = gamma[m * C_CH + c] * rsqrtf(var[m * C_CH + c] + 1e-5f);

    if (t < 169) {
        int i = t / 13, j = t % 13;
        float val = inv[0] * w_lk[c * 169 + t];

        const float* ws[6] = {w_b0, w_b1, w_b2, w_b3, w_b4, w_b5};
        const int ks[6] = {5, 7, 7, 3, 3, 3};
        const int rs[6] = {1, 1, 2, 3, 4, 5};
#pragma unroll
        for (int b = 0; b < 6; b++) {
            int k = ks[b], r = rs[b];
            int span = r * (k - 1) + 1;
            int off = (13 - span) / 2;           // center the dilated kernel
            int ai = i - off, aj = j - off;
            if (ai >= 0 && aj >= 0 && (ai % r) == 0 && (aj % r) == 0) {
                int a = ai / r, bb = aj / r;
                if (a < k && bb < k)
                    val += inv[b + 1] * ws[b][c * k * k + a * k + bb];
            }
        }
        float2 d2 = make_float2(val, val);
        g_Wd[c * W_U64_PER_IMG + i * WSTRIDE + j] =
            *reinterpret_cast<unsigned long long*>(&d2);
    } else if (t < 169 + 39) {
        // zero padding taps 13..15 of each row
        int u = t - 169;
        int i = u / 3, j = 13 + u % 3;
        g_Wd[c * W_U64_PER_IMG + i * WSTRIDE + j] = 0ull;
    }
    if (t == 0) {
        float bsum = 0.f;
#pragma unroll
        for (int m = 0; m < 7; m++)
            bsum += beta[m * C_CH + c] - mean[m * C_CH + c] * inv[m];
        g_bias[c] = bsum;
    }
}

// ---------------------------------------------------------------------------
// Packed fp32 helpers (FFMA2 — PTX-only on sm_103a)
// ---------------------------------------------------------------------------
__device__ __forceinline__ unsigned long long pk2(float lo, float hi) {
    unsigned long long r;
    asm("mov.b64 %0, {%1,%2};" : "=l"(r) : "f"(lo), "f"(hi));
    return r;
}
__device__ __forceinline__ void fma2(unsigned long long& a,
                                     unsigned long long x,
                                     unsigned long long w) {
    asm("fma.rn.f32x2 %0, %1, %2, %0;" : "+l"(a) : "l"(x), "l"(w));
}

// ---------------------------------------------------------------------------
// Process one input row: load + pack once, fan out to NA accumulator rows.
// acc[a] corresponds to weight row (wrow0 - a). No guards: caller guarantees
// all NA rows are in range.
// ---------------------------------------------------------------------------
template <int NA>
__device__ __forceinline__ void proc_row(const float* __restrict__ rowptr,
                                         const unsigned long long* __restrict__ mw,
                                         int wrow0,
                                         unsigned long long (*acc)[4]) {
    const float2* rp = reinterpret_cast<const float2*>(rowptr);
    float2 f[10];
#pragma unroll
    for (int k = 0; k < 10; k++) f[k] = rp[k];      // 10x LDS.64

    unsigned long long p[19];
#pragma unroll
    for (int k = 0; k < 10; k++) p[2 * k] = pk2(f[k].x, f[k].y);
#pragma unroll
    for (int k = 0; k < 9; k++) p[2 * k + 1] = pk2(f[k].y, f[k + 1].x);

#pragma unroll
    for (int a = 0; a < NA; a++) {
        const unsigned long long* wr = mw + (wrow0 - a) * WSTRIDE;
        const ulonglong2* wr2 = reinterpret_cast<const ulonglong2*>(wr);
#pragma unroll
        for (int jj = 0; jj < 6; jj++) {            // taps 2jj, 2jj+1
            ulonglong2 wv = wr2[jj];                // LDS.128 (broadcast)
            fma2(acc[a][0], p[2 * jj],     wv.x);
            fma2(acc[a][1], p[2 * jj + 2], wv.x);
            fma2(acc[a][2], p[2 * jj + 4], wv.x);
            fma2(acc[a][3], p[2 * jj + 6], wv.x);
            fma2(acc[a][0], p[2 * jj + 1], wv.y);
            fma2(acc[a][1], p[2 * jj + 3], wv.y);
            fma2(acc[a][2], p[2 * jj + 5], wv.y);
            fma2(acc[a][3], p[2 * jj + 7], wv.y);
        }
        unsigned long long w12 = wr[12];            // tap 12 (LDS.64)
        fma2(acc[a][0], p[12], w12);
        fma2(acc[a][1], p[14], w12);
        fma2(acc[a][2], p[16], w12);
        fma2(acc[a][3], p[18], w12);
    }
}

// ---------------------------------------------------------------------------
// Kernel 2: depthwise 13x13 conv + bias.
// Block = 4 (n,c) images. Per image: 56 threads = 7 x-tiles (8 wide) x 8 ty.
// Thread strip = 8 wide x 7 rows, computed in two passes (rows 0-3, rows 4-6)
// to bound register pressure. Passes are FULLY unrolled for cross-row
// load/compute overlap.
// ---------------------------------------------------------------------------
extern __shared__ char s_raw[];

__global__ __launch_bounds__(THREADS, 2)
void conv13_kernel(const float* __restrict__ x, float* __restrict__ out) {
    float* s_in = reinterpret_cast<float*>(s_raw);
    unsigned long long* s_w =
        reinterpret_cast<unsigned long long*>(s_raw + SMEM_IN_BYTES);

    int t = threadIdx.x;
    int img_l = t / 56;
    int s = t % 56;
    int tx = s % 7, ty = s / 7;
    int x0 = tx * 8;
    int y0 = ty * 7;

    int img = blockIdx.x * IMG_PER_BLK + img_l;   // flat (n*C + c)
    int c = img % C_CH;

    float* my = s_in + img_l * (PH * PH);
    unsigned long long* mw = s_w + img_l * W_U64_PER_IMG;
    const float* gx = x + (size_t)img * (HW * HW);

    // Stage merged weights: 208 u64 = 104 ulonglong2 per image (guarded).
    {
        const ulonglong2* src =
            reinterpret_cast<const ulonglong2*>(g_Wd + (size_t)c * W_U64_PER_IMG);
        ulonglong2* dst = reinterpret_cast<ulonglong2*>(mw);
        for (int k = s; k < W_U64_PER_IMG / 2; k += 56)
            dst[k] = __ldg(src + k);
    }

    // Stage input: vector zero-fill padded tile, then coalesced float2
    // interior copy (constant-divisor indexing, no runtime div).
    {
        float4* z = reinterpret_cast<float4*>(my);
        for (int k = s; k < (PH * PH) / 4; k += 56)        // 1156 float4
            z[k] = make_float4(0.f, 0.f, 0.f, 0.f);
    }
    __syncthreads();
    {
        int col2 = s % 28;          // column pair 0..27
        int r0 = s / 28;            // 0 or 1
        const float2* g2 = reinterpret_cast<const float2*>(gx);
#pragma unroll
        for (int k = 0; k < 28; k++) {
            int r = r0 + 2 * k;
            float2 v = __ldg(g2 + r * 28 + col2);
            *reinterpret_cast<float2*>(my + (r + PAD) * PH + PAD + 2 * col2) = v;
        }
    }
    __syncthreads();

    float bb = __ldg(&g_bias[c]);
    unsigned long long bias2 = pk2(bb, bb);

    const float* rbase = my + y0 * PH + x0;   // padded coords
    float* obase = out + (size_t)img * (HW * HW);

    // ===================== Pass A: output rows d = 0..3 =====================
    {
        unsigned long long acc[4][4];
#pragma unroll
        for (int a = 0; a < 4; a++)
#pragma unroll
            for (int q = 0; q < 4; q++) acc[a][q] = bias2;

        // ramp-up: ir = 0,1,2
        proc_row<1>(rbase + 0 * PH, mw, 0, &acc[0]);
        proc_row<2>(rbase + 1 * PH, mw, 1, &acc[0]);
        proc_row<3>(rbase + 2 * PH, mw, 2, &acc[0]);
        // steady: ir = 3..12, all 4 rows active (FULLY unrolled)
#pragma unroll
        for (int ir = 3; ir <= 12; ir++)
            proc_row<4>(rbase + ir * PH, mw, ir, &acc[0]);
        // ramp-down: ir = 13,14,15
        proc_row<3>(rbase + 13 * PH, mw, 12, &acc[1]);
        proc_row<2>(rbase + 14 * PH, mw, 12, &acc[2]);
        proc_row<1>(rbase + 15 * PH, mw, 12, &acc[3]);

#pragma unroll
        for (int d = 0; d < 4; d++) {
            ulonglong2* orow = reinterpret_cast<ulonglong2*>(
                obase + (y0 + d) * HW + x0);           // 16B aligned
            orow[0] = make_ulonglong2(acc[d][0], acc[d][1]);
            orow[1] = make_ulonglong2(acc[d][2], acc[d][3]);
        }
    }

    // ===================== Pass B: output rows d = 4..6 =====================
    {
        unsigned long long acc[3][4];
#pragma unroll
        for (int a = 0; a < 3; a++)
#pragma unroll
            for (int q = 0; q < 4; q++) acc[a][q] = bias2;

        // ramp-up: ir = 4,5   (acc[a] = output row 4+a)
        proc_row<1>(rbase + 4 * PH, mw, 0, &acc[0]);
        proc_row<2>(rbase + 5 * PH, mw, 1, &acc[0]);
        // steady: ir = 6..16, all 3 rows active (wrow0 = ir-4, FULLY unrolled)
#pragma unroll
        for (int ir = 6; ir <= 16; ir++)
            proc_row<3>(rbase + ir * PH, mw, ir - 4, &acc[0]);
        // ramp-down: ir = 17,18
        proc_row<2>(rbase + 17 * PH, mw, 12, &acc[1]);
        proc_row<1>(rbase + 18 * PH, mw, 12, &acc[2]);

#pragma unroll
        for (int d = 0; d < 3; d++) {
            ulonglong2* orow = reinterpret_cast<ulonglong2*>(
                obase + (y0 + 4 + d) * HW + x0);
            orow[0] = make_ulonglong2(acc[d][0], acc[d][1]);
            orow[1] = make_ulonglong2(acc[d][2], acc[d][3]);
        }
    }
}

// ---------------------------------------------------------------------------
extern "C" void kernel_launch(void* const* d_in, const int* in_sizes, int n_in,
                              void* d_out, int out_size) {
    const float* x    = (const float*)d_in[0];
    const float* w_lk = (const float*)d_in[1];
    const float* w_b0 = (const float*)d_in[2];
    const float* w_b1 = (const float*)d_in[3];
    const float* w_b2 = (const float*)d_in[4];
    const float* w_b3 = (const float*)d_in[5];
    const float* w_b4 = (const float*)d_in[6];
    const float* w_b5 = (const float*)d_in[7];
    const float* gam  = (const float*)d_in[8];
    const float* bet  = (const float*)d_in[9];
    const float* mea  = (const float*)d_in[10];
    const float* var  = (const float*)d_in[11];
    float* out = (float*)d_out;

    merge_kernel<<<C_CH, 224>>>(w_lk, w_b0, w_b1, w_b2, w_b3, w_b4, w_b5,
                                gam, bet, mea, var);

    cudaFuncSetAttribute(conv13_kernel,
                         cudaFuncAttributeMaxDynamicSharedMemorySize,
                         SMEM_BYTES);
    int grid = (NB * C_CH) / IMG_PER_BLK;  // 1536
    conv13_kernel<<<grid, THREADS, SMEM_BYTES>>>(x, out);
}

// round 7
// speedup vs baseline: 4.9869x; 4.9869x over previous
#include <cuda_runtime.h>
#include <cstdint>

// ---------------------------------------------------------------------------
// DilatedReparamBlock fused: merge 7 BN(dwconv) branches into one exact 13x13
// depthwise conv + bias, then a single packed-fp32 (fma.rn.f32x2) conv.
// Three-pass (d=0-1, 2-3, 4-6) input-row-outer mainloop with EXPLICIT
// double-buffered row prefetch inside unroll-1 steady loops: bounded register
// window (no spills), LDS latency hidden under the FFMA2 wall.
// x: [16, 384, 56, 56] fp32 -> out same shape.
// ---------------------------------------------------------------------------

#define C_CH 384
#define NB 16
#define HW 56
#define PAD 6
#define PH 68                  // 56 + 2*6 padded tile
#define IMG_PER_BLK 4
#define THREADS 224            // 4 images * 56 threads (7 x-tiles * 8 y-tiles)
#define WSTRIDE 16             // u64 (dup-weight taps) per weight row (128B)
#define W_U64_PER_IMG (13 * WSTRIDE)                    // 208
#define SMEM_IN_BYTES (IMG_PER_BLK * PH * PH * 4)       // 73984
#define SMEM_W_BYTES  (IMG_PER_BLK * W_U64_PER_IMG * 8) // 6656
#define SMEM_BYTES    (SMEM_IN_BYTES + SMEM_W_BYTES)    // 80640

// Merged weights: per channel, 13 rows x WSTRIDE u64; entry j (j<13) is the
// tap value DUPLICATED (w,w) so it is a ready FFMA2 b-operand.
__device__ unsigned long long g_Wd[C_CH * W_U64_PER_IMG];
__device__ float g_bias[C_CH];

// ---------------------------------------------------------------------------
// Kernel 1: fold the 7 BN(dwconv) branches into one 13x13 kernel + bias.
// ---------------------------------------------------------------------------
__global__ void merge_kernel(const float* __restrict__ w_lk,
                             const float* __restrict__ w_b0,
                             const float* __restrict__ w_b1,
                             const float* __restrict__ w_b2,
                             const float* __restrict__ w_b3,
                             const float* __restrict__ w_b4,
                             const float* __restrict__ w_b5,
                             const float* __restrict__ gamma,
                             const float* __restrict__ beta,
                             const float* __restrict__ mean,
                             const float* __restrict__ var) {
    int c = blockIdx.x;
    int t = threadIdx.x;

    float inv[7];
#pragma unroll
    for (int m = 0; m < 7; m++)
        inv[m] = gamma[m * C_CH + c] * rsqrtf(var[m * C_CH + c] + 1e-5f);

    if (t < 169) {
        int i = t / 13, j = t % 13;
        float val = inv[0] * w_lk[c * 169 + t];

        const float* ws[6] = {w_b0, w_b1, w_b2, w_b3, w_b4, w_b5};
        const int ks[6] = {5, 7, 7, 3, 3, 3};
        const int rs[6] = {1, 1, 2, 3, 4, 5};
#pragma unroll
        for (int b = 0; b < 6; b++) {
            int k = ks[b], r = rs[b];
            int span = r * (k - 1) + 1;
            int off = (13 - span) / 2;           // center the dilated kernel
            int ai = i - off, aj = j - off;
            if (ai >= 0 && aj >= 0 && (ai % r) == 0 && (aj % r) == 0) {
                int a = ai / r, bb = aj / r;
                if (a < k && bb < k)
                    val += inv[b + 1] * ws[b][c * k * k + a * k + bb];
            }
        }
        float2 d2 = make_float2(val, val);
        g_Wd[c * W_U64_PER_IMG + i * WSTRIDE + j] =
            *reinterpret_cast<unsigned long long*>(&d2);
    } else if (t < 169 + 39) {
        // zero padding taps 13..15 of each row
        int u = t - 169;
        int i = u / 3, j = 13 + u % 3;
        g_Wd[c * W_U64_PER_IMG + i * WSTRIDE + j] = 0ull;
    }
    if (t == 0) {
        float bsum = 0.f;
#pragma unroll
        for (int m = 0; m < 7; m++)
            bsum += beta[m * C_CH + c] - mean[m * C_CH + c] * inv[m];
        g_bias[c] = bsum;
    }
}

// ---------------------------------------------------------------------------
// Packed fp32 helpers (FFMA2 — PTX-only on sm_103a)
// ---------------------------------------------------------------------------
__device__ __forceinline__ unsigned long long pk2(float lo, float hi) {
    unsigned long long r;
    asm("mov.b64 %0, {%1,%2};" : "=l"(r) : "f"(lo), "f"(hi));
    return r;
}
__device__ __forceinline__ void fma2(unsigned long long& a,
                                     unsigned long long x,
                                     unsigned long long w) {
    asm("fma.rn.f32x2 %0, %1, %2, %0;" : "+l"(a) : "l"(x), "l"(w));
}

__device__ __forceinline__ void load10(float2* f, const float* rowptr) {
    const float2* rp = reinterpret_cast<const float2*>(rowptr);
#pragma unroll
    for (int k = 0; k < 10; k++) f[k] = rp[k];      // 10x LDS.64
}

// ---------------------------------------------------------------------------
// Pack one (already loaded) input row and fan out to NA accumulator rows.
// acc[a] uses weight row (wrow0 - a). Caller guarantees rows in range.
// ---------------------------------------------------------------------------
template <int NA>
__device__ __forceinline__ void compute_row(const float2* __restrict__ f,
                                            const unsigned long long* __restrict__ mw,
                                            int wrow0,
                                            unsigned long long (*acc)[4]) {
    unsigned long long p[19];
#pragma unroll
    for (int k = 0; k < 10; k++) p[2 * k] = pk2(f[k].x, f[k].y);
#pragma unroll
    for (int k = 0; k < 9; k++) p[2 * k + 1] = pk2(f[k].y, f[k + 1].x);

#pragma unroll
    for (int a = 0; a < NA; a++) {
        const unsigned long long* wr = mw + (wrow0 - a) * WSTRIDE;
        const ulonglong2* wr2 = reinterpret_cast<const ulonglong2*>(wr);
#pragma unroll
        for (int jj = 0; jj < 6; jj++) {            // taps 2jj, 2jj+1
            ulonglong2 wv = wr2[jj];                // LDS.128 (broadcast)
            fma2(acc[a][0], p[2 * jj],     wv.x);
            fma2(acc[a][1], p[2 * jj + 2], wv.x);
            fma2(acc[a][2], p[2 * jj + 4], wv.x);
            fma2(acc[a][3], p[2 * jj + 6], wv.x);
            fma2(acc[a][0], p[2 * jj + 1], wv.y);
            fma2(acc[a][1], p[2 * jj + 3], wv.y);
            fma2(acc[a][2], p[2 * jj + 5], wv.y);
            fma2(acc[a][3], p[2 * jj + 7], wv.y);
        }
        unsigned long long w12 = wr[12];            // tap 12 (LDS.64)
        fma2(acc[a][0], p[12], w12);
        fma2(acc[a][1], p[14], w12);
        fma2(acc[a][2], p[16], w12);
        fma2(acc[a][3], p[18], w12);
    }
}

template <int NA>
__device__ __forceinline__ void proc_row(const float* __restrict__ rowptr,
                                         const unsigned long long* __restrict__ mw,
                                         int wrow0,
                                         unsigned long long (*acc)[4]) {
    float2 f[10];
    load10(f, rowptr);
    compute_row<NA>(f, mw, wrow0, acc);
}

__device__ __forceinline__ void store_rows(float* obase, int y0, int dfirst,
                                           int nd,
                                           const unsigned long long (*acc)[4]) {
    for (int d = 0; d < nd; d++) {
        ulonglong2* orow = reinterpret_cast<ulonglong2*>(
            obase + (y0 + dfirst + d) * HW);         // +x0 folded by caller
        orow[0] = make_ulonglong2(acc[d][0], acc[d][1]);
        orow[1] = make_ulonglong2(acc[d][2], acc[d][3]);
    }
}

// ---------------------------------------------------------------------------
// Kernel 2: depthwise 13x13 conv + bias.
// Block = 4 (n,c) images. Per image: 56 threads = 7 x-tiles (8 wide) x 8 ty.
// Thread strip = 8 wide x 7 rows in three passes (d=0-1, 2-3, 4-6).
// Steady loops: unroll 1 + ping-pong row prefetch (f/g), so each iteration's
// 10 LDS issue while the previous row's FFMA2 wall executes.
// ---------------------------------------------------------------------------
extern __shared__ char s_raw[];

__global__ __launch_bounds__(THREADS, 2)
void conv13_kernel(const float* __restrict__ x, float* __restrict__ out) {
    float* s_in = reinterpret_cast<float*>(s_raw);
    unsigned long long* s_w =
        reinterpret_cast<unsigned long long*>(s_raw + SMEM_IN_BYTES);

    int t = threadIdx.x;
    int img_l = t / 56;
    int s = t % 56;
    int tx = s % 7, ty = s / 7;
    int x0 = tx * 8;
    int y0 = ty * 7;

    int img = blockIdx.x * IMG_PER_BLK + img_l;   // flat (n*C + c)
    int c = img % C_CH;

    float* my = s_in + img_l * (PH * PH);
    unsigned long long* mw = s_w + img_l * W_U64_PER_IMG;
    const float* gx = x + (size_t)img * (HW * HW);

    // Stage merged weights: 208 u64 = 104 ulonglong2 per image (guarded).
    {
        const ulonglong2* src =
            reinterpret_cast<const ulonglong2*>(g_Wd + (size_t)c * W_U64_PER_IMG);
        ulonglong2* dst = reinterpret_cast<ulonglong2*>(mw);
        for (int k = s; k < W_U64_PER_IMG / 2; k += 56)
            dst[k] = __ldg(src + k);
    }

    // Stage input: vector zero-fill padded tile, then coalesced float2
    // interior copy (constant-divisor indexing, no runtime div).
    {
        float4* z = reinterpret_cast<float4*>(my);
        for (int k = s; k < (PH * PH) / 4; k += 56)        // 1156 float4
            z[k] = make_float4(0.f, 0.f, 0.f, 0.f);
    }
    __syncthreads();
    {
        int col2 = s % 28;          // column pair 0..27
        int r0 = s / 28;            // 0 or 1
        const float2* g2 = reinterpret_cast<const float2*>(gx);
#pragma unroll
        for (int k = 0; k < 28; k++) {
            int r = r0 + 2 * k;
            float2 v = __ldg(g2 + r * 28 + col2);
            *reinterpret_cast<float2*>(my + (r + PAD) * PH + PAD + 2 * col2) = v;
        }
    }
    __syncthreads();

    float bb = __ldg(&g_bias[c]);
    unsigned long long bias2 = pk2(bb, bb);

    const float* rbase = my + y0 * PH + x0;   // padded coords
    float* obase = out + (size_t)img * (HW * HW) + x0;

    // =================== Pass 1: output rows d = 0..1 (rows 0..13) ==========
    {
        unsigned long long acc[2][4];
#pragma unroll
        for (int a = 0; a < 2; a++)
#pragma unroll
            for (int q = 0; q < 4; q++) acc[a][q] = bias2;

        proc_row<1>(rbase + 0 * PH, mw, 0, &acc[0]);   // ir=0: d0 only
        float2 f[10], g[10];
        load10(f, rbase + 1 * PH);
#pragma unroll 1
        for (int ir = 1; ir < 12; ir += 2) {           // bodies: 1..12
            load10(g, rbase + (ir + 1) * PH);
            compute_row<2>(f, mw, ir, &acc[0]);
            load10(f, rbase + (ir + 2) * PH);          // last: row 13
            compute_row<2>(g, mw, ir + 1, &acc[0]);
        }
        compute_row<1>(f, mw, 12, &acc[1]);            // ir=13: d1 only
        store_rows(obase, y0, 0, 2, acc);
    }

    // =================== Pass 2: output rows d = 2..3 (rows 2..15) ==========
    {
        unsigned long long acc[2][4];
#pragma unroll
        for (int a = 0; a < 2; a++)
#pragma unroll
            for (int q = 0; q < 4; q++) acc[a][q] = bias2;

        proc_row<1>(rbase + 2 * PH, mw, 0, &acc[0]);   // ir=2: d2 only
        float2 f[10], g[10];
        load10(f, rbase + 3 * PH);
#pragma unroll 1
        for (int ir = 3; ir < 14; ir += 2) {           // bodies: 3..14
            load10(g, rbase + (ir + 1) * PH);
            compute_row<2>(f, mw, ir - 2, &acc[0]);
            load10(f, rbase + (ir + 2) * PH);          // last: row 15
            compute_row<2>(g, mw, ir - 1, &acc[0]);
        }
        compute_row<1>(f, mw, 12, &acc[1]);            // ir=15: d3 only
        store_rows(obase, y0, 2, 2, acc);
    }

    // =================== Pass 3: output rows d = 4..6 (rows 4..18) ==========
    {
        unsigned long long acc[3][4];
#pragma unroll
        for (int a = 0; a < 3; a++)
#pragma unroll
            for (int q = 0; q < 4; q++) acc[a][q] = bias2;

        proc_row<1>(rbase + 4 * PH, mw, 0, &acc[0]);   // ir=4: d4
        proc_row<2>(rbase + 5 * PH, mw, 1, &acc[0]);   // ir=5: d4,d5
        float2 f[10], g[10];
        load10(f, rbase + 6 * PH);
#pragma unroll 1
        for (int ir = 6; ir < 16; ir += 2) {           // bodies: 6..15
            load10(g, rbase + (ir + 1) * PH);
            compute_row<3>(f, mw, ir - 4, &acc[0]);
            load10(f, rbase + (ir + 2) * PH);          // last: row 16
            compute_row<3>(g, mw, ir - 3, &acc[0]);
        }
        compute_row<3>(f, mw, 12, &acc[0]);            // ir=16: d4,d5,d6
        proc_row<2>(rbase + 17 * PH, mw, 12, &acc[1]); // ir=17: d5,d6
        proc_row<1>(rbase + 18 * PH, mw, 12, &acc[2]); // ir=18: d6
        store_rows(obase, y0, 4, 3, acc);
    }
}

// ---------------------------------------------------------------------------
extern "C" void kernel_launch(void* const* d_in, const int* in_sizes, int n_in,
                              void* d_out, int out_size) {
    const float* x    = (const float*)d_in[0];
    const float* w_lk = (const float*)d_in[1];
    const float* w_b0 = (const float*)d_in[2];
    const float* w_b1 = (const float*)d_in[3];
    const float* w_b2 = (const float*)d_in[4];
    const float* w_b3 = (const float*)d_in[5];
    const float* w_b4 = (const float*)d_in[6];
    const float* w_b5 = (const float*)d_in[7];
    const float* gam  = (const float*)d_in[8];
    const float* bet  = (const float*)d_in[9];
    const float* mea  = (const float*)d_in[10];
    const float* var  = (const float*)d_in[11];
    float* out = (float*)d_out;

    merge_kernel<<<C_CH, 224>>>(w_lk, w_b0, w_b1, w_b2, w_b3, w_b4, w_b5,
                                gam, bet, mea, var);

    cudaFuncSetAttribute(conv13_kernel,
                         cudaFuncAttributeMaxDynamicSharedMemorySize,
                         SMEM_BYTES);
    int grid = (NB * C_CH) / IMG_PER_BLK;  // 1536
    conv13_kernel<<<grid, THREADS, SMEM_BYTES>>>(x, out);
}